// round 5
// baseline (speedup 1.0000x reference)
#include <cuda_runtime.h>
#include <math.h>
#include <stdint.h>

#define B_SZ 64
#define L_SEQ 196
#define D_MODEL 192
#define DEPTH 24
#define D_INNER 384
#define D_STATE 16
#define D_CONV 4
#define DT_RANK 12
#define N_CLS 1000
#define XPROJ_N (DT_RANK + 2*D_STATE)   // 44
#define ROWS (B_SZ*L_SEQ)               // 12544
#define K_PATCH 768                      // 3*16*16

// ---------------- scratch (device globals, no allocation) ----------------
__device__ float g_hidden[ROWS*D_MODEL];
__device__ float g_residual[ROWS*D_MODEL];
__device__ float g_hn[ROWS*D_MODEL];
__device__ float g_xz[ROWS*2*D_INNER];      // also reused as im2col buffer (ROWS*768)
__device__ float g_xb[ROWS*D_INNER];
__device__ float g_xdbl[ROWS*XPROJ_N];
__device__ float g_y[ROWS*D_INNER];
// tf32-rounded weight copies
__device__ float g_wpatch[D_MODEL*K_PATCH];
__device__ float g_win[DEPTH*2*D_INNER*D_MODEL];
__device__ float g_wx[DEPTH*XPROJ_N*D_INNER];
__device__ float g_wout[DEPTH*D_MODEL*D_INNER];

// ================= tf32 helpers =================
__device__ __forceinline__ uint32_t f2tf32(float f) {
    uint32_t o;
    asm("cvt.rna.tf32.f32 %0, %1;" : "=r"(o) : "f"(f));
    return o;
}
__device__ __forceinline__ float tf32r(float f) {
    return __uint_as_float(f2tf32(f));
}

__global__ void round_tf32_kernel(const float* __restrict__ src, float* __restrict__ dst, int n) {
    int i = blockIdx.x * blockDim.x + threadIdx.x;
    int stride = gridDim.x * blockDim.x;
    for (; i < n; i += stride) dst[i] = tf32r(src[i]);
}

// ================= mma.sync tf32 GEMM =================
// C[m][n] = sum_k A[m*K+k]*W[n*K+k] (+bias[n])
// BM=128, BN=64, BK=32 floats. 256 thr = 8 warps (4M x 2N), warp tile 32x32.
// W must be tf32-pre-rounded. A pre-rounded iff APRE.

#define GA_STRIDE 36                     // row pitch in floats (32 + 4 pad)
#define STAGE_BYTES (128*GA_STRIDE*4 + 64*GA_STRIDE*4)   // A tile + W tile = 27648
#define SMEM_W_OFF (128*GA_STRIDE)       // floats

__device__ __forceinline__ uint32_t smem_u32(const void* p) {
    uint32_t a;
    asm("{ .reg .u64 t; cvta.to.shared.u64 t, %1; cvt.u32.u64 %0, t; }" : "=r"(a) : "l"(p));
    return a;
}
#define CP_ASYNC(dst, src, sz) \
    asm volatile("cp.async.cg.shared.global [%0], [%1], 16, %2;" :: "r"(dst), "l"(src), "r"(sz))
#define CP_COMMIT() asm volatile("cp.async.commit_group;" ::: "memory")
#define CP_WAIT(n)  asm volatile("cp.async.wait_group %0;" :: "n"(n) : "memory")

__device__ __forceinline__ void mma1688(float* c, const uint32_t* a, const uint32_t* b) {
    asm volatile(
        "mma.sync.aligned.m16n8k8.row.col.f32.tf32.tf32.f32 "
        "{%0,%1,%2,%3}, {%4,%5,%6,%7}, {%8,%9}, {%0,%1,%2,%3};"
        : "+f"(c[0]), "+f"(c[1]), "+f"(c[2]), "+f"(c[3])
        : "r"(a[0]), "r"(a[1]), "r"(a[2]), "r"(a[3]), "r"(b[0]), "r"(b[1]));
}

template<bool APRE>
__global__ __launch_bounds__(256) void gemm_mma(
        const float* __restrict__ A, const float* __restrict__ W,
        float* __restrict__ C, int M, int N, int K,
        const float* __restrict__ bias) {
    extern __shared__ float smem[];      // [2 stages][A 128x36 | W 64x36]
    int tid = threadIdx.x;
    int wid = tid >> 5, lid = tid & 31;
    int wm = wid & 3, wn = wid >> 2;     // warp coords: 4 x 2
    int group = lid >> 2, tq = lid & 3;
    int bm = blockIdx.y * 128, bn = blockIdx.x * 64;

    uint32_t sb = smem_u32(smem);
    int nk = K >> 5;

    auto load_stage = [&](int st, int kc) {
        uint32_t base = sb + st * STAGE_BYTES;
        #pragma unroll
        for (int i = 0; i < 4; i++) {
            int q = tid * 4 + i;
            int row = q >> 3, quad = q & 7;
            uint32_t dst = base + (row * GA_STRIDE + quad * 4) * 4;
            const float* src = A + (size_t)(bm + row) * K + (size_t)kc * 32 + quad * 4;
            CP_ASYNC(dst, src, 16);
        }
        #pragma unroll
        for (int i = 0; i < 2; i++) {
            int q = tid * 2 + i;
            int row = q >> 3, quad = q & 7;
            int n = bn + row;
            uint32_t dst = base + (SMEM_W_OFF + row * GA_STRIDE + quad * 4) * 4;
            const float* src = (n < N) ? (W + (size_t)n * K + (size_t)kc * 32 + quad * 4) : W;
            CP_ASYNC(dst, src, (n < N) ? 16 : 0);
        }
        CP_COMMIT();
    };

    float acc[2][4][4] = {};

    load_stage(0, 0);
    for (int k0 = 0; k0 < nk; k0++) {
        if (k0 + 1 < nk) { load_stage((k0 + 1) & 1, k0 + 1); CP_WAIT(1); }
        else             { CP_WAIT(0); }
        __syncthreads();
        const float* sA = smem + (size_t)(k0 & 1) * (STAGE_BYTES / 4);
        const float* sW = sA + SMEM_W_OFF;
        #pragma unroll
        for (int kk = 0; kk < 32; kk += 8) {
            uint32_t a[2][4], b[4][2];
            #pragma unroll
            for (int mi = 0; mi < 2; mi++) {
                int r = wm * 32 + mi * 16 + group;
                if (APRE) {
                    a[mi][0] = __float_as_uint(sA[r * GA_STRIDE + kk + tq]);
                    a[mi][1] = __float_as_uint(sA[(r + 8) * GA_STRIDE + kk + tq]);
                    a[mi][2] = __float_as_uint(sA[r * GA_STRIDE + kk + tq + 4]);
                    a[mi][3] = __float_as_uint(sA[(r + 8) * GA_STRIDE + kk + tq + 4]);
                } else {
                    a[mi][0] = f2tf32(sA[r * GA_STRIDE + kk + tq]);
                    a[mi][1] = f2tf32(sA[(r + 8) * GA_STRIDE + kk + tq]);
                    a[mi][2] = f2tf32(sA[r * GA_STRIDE + kk + tq + 4]);
                    a[mi][3] = f2tf32(sA[(r + 8) * GA_STRIDE + kk + tq + 4]);
                }
            }
            #pragma unroll
            for (int ni = 0; ni < 4; ni++) {
                int r = wn * 32 + ni * 8 + group;
                b[ni][0] = __float_as_uint(sW[r * GA_STRIDE + kk + tq]);
                b[ni][1] = __float_as_uint(sW[r * GA_STRIDE + kk + tq + 4]);
            }
            #pragma unroll
            for (int mi = 0; mi < 2; mi++)
                #pragma unroll
                for (int ni = 0; ni < 4; ni++)
                    mma1688(acc[mi][ni], a[mi], b[ni]);
        }
        __syncthreads();
    }

    #pragma unroll
    for (int mi = 0; mi < 2; mi++) {
        int m0 = bm + wm * 32 + mi * 16 + group;
        #pragma unroll
        for (int ni = 0; ni < 4; ni++) {
            int n0 = bn + wn * 32 + ni * 8 + tq * 2;
            if (n0 < N) {
                float bx = 0.f, by = 0.f;
                if (bias) { bx = bias[n0]; by = bias[n0 + 1]; }
                float2 o0 = make_float2(acc[mi][ni][0] + bx, acc[mi][ni][1] + by);
                float2 o1 = make_float2(acc[mi][ni][2] + bx, acc[mi][ni][3] + by);
                *(float2*)&C[(size_t)m0 * N + n0] = o0;
                *(float2*)&C[(size_t)(m0 + 8) * N + n0] = o1;
            }
        }
    }
}

// ---------------- im2col for patch embed (tf32-rounded output) ----------------
__global__ void im2col_kernel(const float* __restrict__ x, float* __restrict__ col) {
    int idx = blockIdx.x * blockDim.x + threadIdx.x;
    if (idx >= ROWS * K_PATCH) return;
    int k  = idx % K_PATCH;
    int bl = idx / K_PATCH;
    int l  = bl % L_SEQ;
    int b  = bl / L_SEQ;
    int c  = k / 256;
    int rem = k % 256;
    int i = rem / 16, j = rem % 16;
    int ph = l / 14, pw = l % 14;
    col[idx] = tf32r(x[((b*3 + c)*224 + ph*16 + i)*224 + pw*16 + j]);
}

// ---------------- fused residual add + LayerNorm (hn tf32-rounded) ----------------
__global__ void add_ln_kernel(const float* __restrict__ hidden, float* __restrict__ residual,
                              float* __restrict__ hn, const float* __restrict__ w,
                              const float* __restrict__ b, int first) {
    int row = blockIdx.x;
    int t = threadIdx.x;               // 192 threads
    int idx = row*D_MODEL + t;
    float h = hidden[idx];
    float r = first ? h : (residual[idx] + h);
    residual[idx] = r;
    __shared__ float red[6];
    float s = r;
    #pragma unroll
    for (int o = 16; o > 0; o >>= 1) s += __shfl_xor_sync(0xffffffffu, s, o);
    if ((t & 31) == 0) red[t >> 5] = s;
    __syncthreads();
    float mean = (red[0]+red[1]+red[2]+red[3]+red[4]+red[5]) * (1.f/192.f);
    __syncthreads();
    float dv = r - mean;
    s = dv*dv;
    #pragma unroll
    for (int o = 16; o > 0; o >>= 1) s += __shfl_xor_sync(0xffffffffu, s, o);
    if ((t & 31) == 0) red[t >> 5] = s;
    __syncthreads();
    float var = (red[0]+red[1]+red[2]+red[3]+red[4]+red[5]) * (1.f/192.f);
    hn[idx] = tf32r(dv * rsqrtf(var + 1e-5f) * w[t] + b[t]);
}

// ---------------- causal depthwise conv1d (k=4) + SiLU ----------------
__global__ void conv_silu_kernel(const float* __restrict__ xz, const float* __restrict__ cw,
                                 const float* __restrict__ cb, float* __restrict__ xb) {
    int idx = blockIdx.x * blockDim.x + threadIdx.x;
    if (idx >= ROWS * D_INNER) return;
    int d  = idx % D_INNER;
    int bl = idx / D_INNER;
    int l  = bl % L_SEQ;
    float acc = cb[d];
    #pragma unroll
    for (int j = 0; j < D_CONV; j++) {
        int ll = l - (D_CONV-1) + j;
        if (ll >= 0) acc += cw[d*D_CONV + j] * xz[(size_t)(bl - l + ll)*(2*D_INNER) + d];
    }
    float sig = 1.f / (1.f + __expf(-acc));
    xb[idx] = acc * sig;
}

// ---------------- selective scan: fused dt-proj + softplus + scan + z-gate ----------------
__global__ __launch_bounds__(128) void scan_kernel(
        const float* __restrict__ xb, const float* __restrict__ xdbl,
        const float* __restrict__ xz, const float* __restrict__ A_log,
        const float* __restrict__ Dskip, const float* __restrict__ dtw,
        const float* __restrict__ dtb, float* __restrict__ y) {
    int b = blockIdx.y;
    int d = blockIdx.x * 128 + threadIdx.x;
    __shared__ float sdbl[L_SEQ][XPROJ_N];          // 34496 B
    const float* src = &xdbl[(size_t)b*L_SEQ*XPROJ_N];
    for (int idx = threadIdx.x; idx < L_SEQ*XPROJ_N; idx += 128)
        ((float*)sdbl)[idx] = src[idx];
    __syncthreads();

    float wdt[DT_RANK];
    #pragma unroll
    for (int r = 0; r < DT_RANK; r++) wdt[r] = dtw[d*DT_RANK + r];
    float bdt = dtb[d];
    float a[D_STATE], h[D_STATE];
    #pragma unroll
    for (int n = 0; n < D_STATE; n++) {
        a[n] = -__expf(A_log[d*D_STATE + n]);
        h[n] = 0.f;
    }
    float Dd = Dskip[d];

    size_t base0 = (size_t)b*L_SEQ*D_INNER + d;
    size_t zbase0 = (size_t)b*L_SEQ*(2*D_INNER) + D_INNER + d;
    float u_cur = xb[base0];
    float z_cur = xz[zbase0];
    for (int l = 0; l < L_SEQ; l++) {
        float u = u_cur, z = z_cur;
        if (l + 1 < L_SEQ) {
            u_cur = xb[base0 + (size_t)(l+1)*D_INNER];
            z_cur = xz[zbase0 + (size_t)(l+1)*(2*D_INNER)];
        }
        float dt = bdt;
        #pragma unroll
        for (int r = 0; r < DT_RANK; r++) dt += sdbl[l][r] * wdt[r];
        dt = (dt > 15.f) ? dt : __logf(1.f + __expf(dt));
        float du = dt * u;
        float yv = 0.f;
        #pragma unroll
        for (int n = 0; n < D_STATE; n++) {
            h[n] = __expf(dt * a[n]) * h[n] + du * sdbl[l][DT_RANK + n];
            yv  += h[n] * sdbl[l][DT_RANK + D_STATE + n];
        }
        yv += u * Dd;
        float sig = 1.f / (1.f + __expf(-z));
        y[base0 + (size_t)l*D_INNER] = tf32r(yv * (z * sig));
    }
}

// ---------------- final: last-token residual+LN+head ----------------
__global__ void final_kernel(const float* __restrict__ residual, const float* __restrict__ hidden,
                             const float* __restrict__ nw, const float* __restrict__ nb,
                             const float* __restrict__ hw, const float* __restrict__ hb,
                             float* __restrict__ out) {
    int b = blockIdx.x;
    int t = threadIdx.x;               // 256 threads
    __shared__ float sh[D_MODEL];
    __shared__ float red[8];
    int row = b*L_SEQ + (L_SEQ - 1);
    float v = 0.f;
    if (t < D_MODEL) v = residual[row*D_MODEL + t] + hidden[row*D_MODEL + t];
    float s = v;
    #pragma unroll
    for (int o = 16; o > 0; o >>= 1) s += __shfl_xor_sync(0xffffffffu, s, o);
    if ((t & 31) == 0) red[t >> 5] = s;
    __syncthreads();
    float mean = 0.f;
    #pragma unroll
    for (int i = 0; i < 8; i++) mean += red[i];
    mean *= (1.f/192.f);
    __syncthreads();
    float dv = (t < D_MODEL) ? (v - mean) : 0.f;
    s = dv*dv;
    #pragma unroll
    for (int o = 16; o > 0; o >>= 1) s += __shfl_xor_sync(0xffffffffu, s, o);
    if ((t & 31) == 0) red[t >> 5] = s;
    __syncthreads();
    float var = 0.f;
    #pragma unroll
    for (int i = 0; i < 8; i++) var += red[i];
    var *= (1.f/192.f);
    if (t < D_MODEL) sh[t] = dv * rsqrtf(var + 1e-5f) * nw[t] + nb[t];
    __syncthreads();
    for (int o = t; o < N_CLS; o += 256) {
        float acc = hb[o];
        #pragma unroll 4
        for (int k = 0; k < D_MODEL; k++) acc += sh[k] * hw[o*D_MODEL + k];
        out[b*N_CLS + o] = acc;
    }
}

extern "C" void kernel_launch(void* const* d_in, const int* in_sizes, int n_in,
                              void* d_out, int out_size) {
    const float* x        = (const float*)d_in[0];
    const float* patch_w  = (const float*)d_in[1];
    const float* patch_b  = (const float*)d_in[2];
    const float* in_w     = (const float*)d_in[3];
    const float* conv_w   = (const float*)d_in[4];
    const float* conv_b   = (const float*)d_in[5];
    const float* xproj_w  = (const float*)d_in[6];
    const float* dt_w     = (const float*)d_in[7];
    const float* dt_b     = (const float*)d_in[8];
    const float* A_log    = (const float*)d_in[9];
    const float* D_skip   = (const float*)d_in[10];
    const float* out_w    = (const float*)d_in[11];
    const float* norm_w   = (const float*)d_in[12];
    const float* norm_b   = (const float*)d_in[13];
    const float* normf_w  = (const float*)d_in[14];
    const float* normf_b  = (const float*)d_in[15];
    const float* head_w   = (const float*)d_in[16];
    const float* head_b   = (const float*)d_in[17];
    float* out = (float*)d_out;

    float *hidden, *residual, *hn, *xz, *xb, *xdbl, *y;
    float *wpatch, *win, *wx, *wout;
    cudaGetSymbolAddress((void**)&hidden,   g_hidden);
    cudaGetSymbolAddress((void**)&residual, g_residual);
    cudaGetSymbolAddress((void**)&hn,       g_hn);
    cudaGetSymbolAddress((void**)&xz,       g_xz);
    cudaGetSymbolAddress((void**)&xb,       g_xb);
    cudaGetSymbolAddress((void**)&xdbl,     g_xdbl);
    cudaGetSymbolAddress((void**)&y,        g_y);
    cudaGetSymbolAddress((void**)&wpatch,   g_wpatch);
    cudaGetSymbolAddress((void**)&win,      g_win);
    cudaGetSymbolAddress((void**)&wx,       g_wx);
    cudaGetSymbolAddress((void**)&wout,     g_wout);

    const int smem_bytes = 2 * STAGE_BYTES;   // 55296
    cudaFuncSetAttribute(gemm_mma<true>,  cudaFuncAttributeMaxDynamicSharedMemorySize, smem_bytes);
    cudaFuncSetAttribute(gemm_mma<false>, cudaFuncAttributeMaxDynamicSharedMemorySize, smem_bytes);

    // pre-round all GEMM weights to tf32 once (same values the MMA consumed before)
    round_tf32_kernel<<<512, 256>>>(patch_w, wpatch, D_MODEL*K_PATCH);
    round_tf32_kernel<<<2048, 256>>>(in_w,   win,    DEPTH*2*D_INNER*D_MODEL);
    round_tf32_kernel<<<512, 256>>>(xproj_w, wx,     DEPTH*XPROJ_N*D_INNER);
    round_tf32_kernel<<<1024, 256>>>(out_w,  wout,   DEPTH*D_MODEL*D_INNER);

    // patch embed: im2col (into xz scratch, tf32-rounded) + GEMM
    im2col_kernel<<<(ROWS*K_PATCH + 255)/256, 256>>>(x, xz);
    gemm_mma<true><<<dim3(3, ROWS/128), 256, smem_bytes>>>(xz, wpatch, hidden, ROWS, D_MODEL, K_PATCH, patch_b);

    for (int i = 0; i < DEPTH; i++) {
        add_ln_kernel<<<ROWS, D_MODEL>>>(hidden, residual, hn,
                                         norm_w + i*D_MODEL, norm_b + i*D_MODEL, i == 0);
        gemm_mma<true><<<dim3(12, ROWS/128), 256, smem_bytes>>>(hn, win + (size_t)i*2*D_INNER*D_MODEL,
                                                                xz, ROWS, 2*D_INNER, D_MODEL, nullptr);
        conv_silu_kernel<<<(ROWS*D_INNER + 255)/256, 256>>>(xz, conv_w + i*D_INNER*D_CONV,
                                                            conv_b + i*D_INNER, xb);
        gemm_mma<false><<<dim3(1, ROWS/128), 256, smem_bytes>>>(xb, wx + (size_t)i*XPROJ_N*D_INNER,
                                                                xdbl, ROWS, XPROJ_N, D_INNER, nullptr);
        scan_kernel<<<dim3(D_INNER/128, B_SZ), 128>>>(xb, xdbl, xz,
                                                      A_log + (size_t)i*D_INNER*D_STATE,
                                                      D_skip + i*D_INNER,
                                                      dt_w + (size_t)i*D_INNER*DT_RANK,
                                                      dt_b + i*D_INNER, y);
        gemm_mma<true><<<dim3(3, ROWS/128), 256, smem_bytes>>>(y, wout + (size_t)i*D_MODEL*D_INNER,
                                                               hidden, ROWS, D_MODEL, D_INNER, nullptr);
    }

    final_kernel<<<B_SZ, 256>>>(residual, hidden, normf_w, normf_b, head_w, head_b, out);
}

// round 7
// speedup vs baseline: 1.0116x; 1.0116x over previous
#include <cuda_runtime.h>
#include <math.h>
#include <stdint.h>

#define B_SZ 64
#define L_SEQ 196
#define D_MODEL 192
#define DEPTH 24
#define D_INNER 384
#define D_STATE 16
#define D_CONV 4
#define DT_RANK 12
#define N_CLS 1000
#define XPROJ_N (DT_RANK + 2*D_STATE)   // 44
#define ROWS (B_SZ*L_SEQ)               // 12544
#define K_PATCH 768                      // 3*16*16

// ---------------- scratch (device globals, no allocation) ----------------
__device__ float g_hidden[ROWS*D_MODEL];
__device__ float g_residual[ROWS*D_MODEL];
__device__ float g_hn[ROWS*D_MODEL];
__device__ float g_xz[ROWS*2*D_INNER];      // also reused as im2col buffer (ROWS*768)
__device__ float g_xb[ROWS*D_INNER];
__device__ float g_xdbl[ROWS*XPROJ_N];
__device__ float g_y[ROWS*D_INNER];
// tf32-rounded weight copies
__device__ float g_wpatch[D_MODEL*K_PATCH];
__device__ float g_win[DEPTH*2*D_INNER*D_MODEL];
__device__ float g_wx[DEPTH*XPROJ_N*D_INNER];
__device__ float g_wout[DEPTH*D_MODEL*D_INNER];

// ================= tf32 helpers =================
__device__ __forceinline__ uint32_t f2tf32(float f) {
    uint32_t o;
    asm("cvt.rna.tf32.f32 %0, %1;" : "=r"(o) : "f"(f));
    return o;
}
__device__ __forceinline__ float tf32r(float f) {
    return __uint_as_float(f2tf32(f));
}

__global__ void round_tf32_kernel(const float* __restrict__ src, float* __restrict__ dst, int n) {
    int i = blockIdx.x * blockDim.x + threadIdx.x;
    int stride = gridDim.x * blockDim.x;
    for (; i < n; i += stride) dst[i] = tf32r(src[i]);
}

// ================= mma.sync tf32 GEMM =================
// C[m][n] = sum_k A[m*K+k]*W[n*K+k] (+bias[n])
// BM=128, BN=64, BK=32 floats. 256 thr = 8 warps (4M x 2N), warp tile 32x32.

#define GA_STRIDE 36                     // row pitch in floats (MUST be mult of 4 for cp.async.16)
#define STAGE_BYTES ((128+64)*GA_STRIDE*4)   // 27648
#define SMEM_W_OFF (128*GA_STRIDE)       // floats

__device__ __forceinline__ uint32_t smem_u32(const void* p) {
    uint32_t a;
    asm("{ .reg .u64 t; cvta.to.shared.u64 t, %1; cvt.u32.u64 %0, t; }" : "=r"(a) : "l"(p));
    return a;
}
#define CP_ASYNC(dst, src, sz) \
    asm volatile("cp.async.cg.shared.global [%0], [%1], 16, %2;" :: "r"(dst), "l"(src), "r"(sz))
#define CP_COMMIT() asm volatile("cp.async.commit_group;" ::: "memory")
#define CP_WAIT(n)  asm volatile("cp.async.wait_group %0;" :: "n"(n) : "memory")

__device__ __forceinline__ void mma1688(float* c, const uint32_t* a, const uint32_t* b) {
    asm volatile(
        "mma.sync.aligned.m16n8k8.row.col.f32.tf32.tf32.f32 "
        "{%0,%1,%2,%3}, {%4,%5,%6,%7}, {%8,%9}, {%0,%1,%2,%3};"
        : "+f"(c[0]), "+f"(c[1]), "+f"(c[2]), "+f"(c[3])
        : "r"(a[0]), "r"(a[1]), "r"(a[2]), "r"(a[3]), "r"(b[0]), "r"(b[1]));
}

template<bool APRE>
__global__ __launch_bounds__(256, 3) void gemm_mma(
        const float* __restrict__ A, const float* __restrict__ W,
        float* __restrict__ C, int M, int N, int K,
        const float* __restrict__ bias) {
    extern __shared__ float smem[];      // [2 stages][A 128x36 | W 64x36]
    int tid = threadIdx.x;
    int wid = tid >> 5, lid = tid & 31;
    int wm = wid & 3, wn = wid >> 2;     // warp coords: 4 x 2
    int group = lid >> 2, tq = lid & 3;
    int bm = blockIdx.y * 128, bn = blockIdx.x * 64;

    uint32_t sb = smem_u32(smem);
    int nk = K >> 5;

    auto load_stage = [&](int st, int kc) {
        uint32_t base = sb + st * STAGE_BYTES;
        #pragma unroll
        for (int i = 0; i < 4; i++) {
            int q = tid * 4 + i;
            int row = q >> 3, quad = q & 7;
            uint32_t dst = base + (row * GA_STRIDE + quad * 4) * 4;
            const float* src = A + (size_t)(bm + row) * K + (size_t)kc * 32 + quad * 4;
            CP_ASYNC(dst, src, 16);
        }
        #pragma unroll
        for (int i = 0; i < 2; i++) {
            int q = tid * 2 + i;
            int row = q >> 3, quad = q & 7;
            int n = bn + row;
            uint32_t dst = base + (SMEM_W_OFF + row * GA_STRIDE + quad * 4) * 4;
            const float* src = (n < N) ? (W + (size_t)n * K + (size_t)kc * 32 + quad * 4) : W;
            CP_ASYNC(dst, src, (n < N) ? 16 : 0);
        }
        CP_COMMIT();
    };

    float acc[2][4][4] = {};

    load_stage(0, 0);
    for (int k0 = 0; k0 < nk; k0++) {
        if (k0 + 1 < nk) { load_stage((k0 + 1) & 1, k0 + 1); CP_WAIT(1); }
        else             { CP_WAIT(0); }
        __syncthreads();
        const float* sA = smem + (size_t)(k0 & 1) * (STAGE_BYTES / 4);
        const float* sW = sA + SMEM_W_OFF;
        #pragma unroll
        for (int kk = 0; kk < 32; kk += 8) {
            uint32_t a[2][4], b[4][2];
            #pragma unroll
            for (int mi = 0; mi < 2; mi++) {
                int r = wm * 32 + mi * 16 + group;
                if (APRE) {
                    a[mi][0] = __float_as_uint(sA[r * GA_STRIDE + kk + tq]);
                    a[mi][1] = __float_as_uint(sA[(r + 8) * GA_STRIDE + kk + tq]);
                    a[mi][2] = __float_as_uint(sA[r * GA_STRIDE + kk + tq + 4]);
                    a[mi][3] = __float_as_uint(sA[(r + 8) * GA_STRIDE + kk + tq + 4]);
                } else {
                    a[mi][0] = f2tf32(sA[r * GA_STRIDE + kk + tq]);
                    a[mi][1] = f2tf32(sA[(r + 8) * GA_STRIDE + kk + tq]);
                    a[mi][2] = f2tf32(sA[r * GA_STRIDE + kk + tq + 4]);
                    a[mi][3] = f2tf32(sA[(r + 8) * GA_STRIDE + kk + tq + 4]);
                }
            }
            #pragma unroll
            for (int ni = 0; ni < 4; ni++) {
                int r = wn * 32 + ni * 8 + group;
                b[ni][0] = __float_as_uint(sW[r * GA_STRIDE + kk + tq]);
                b[ni][1] = __float_as_uint(sW[r * GA_STRIDE + kk + tq + 4]);
            }
            #pragma unroll
            for (int mi = 0; mi < 2; mi++)
                #pragma unroll
                for (int ni = 0; ni < 4; ni++)
                    mma1688(acc[mi][ni], a[mi], b[ni]);
        }
        __syncthreads();
    }

    #pragma unroll
    for (int mi = 0; mi < 2; mi++) {
        int m0 = bm + wm * 32 + mi * 16 + group;
        #pragma unroll
        for (int ni = 0; ni < 4; ni++) {
            int n0 = bn + wn * 32 + ni * 8 + tq * 2;
            if (n0 < N) {
                float bx = 0.f, by = 0.f;
                if (bias) { bx = bias[n0]; by = bias[n0 + 1]; }
                float2 o0 = make_float2(acc[mi][ni][0] + bx, acc[mi][ni][1] + by);
                float2 o1 = make_float2(acc[mi][ni][2] + bx, acc[mi][ni][3] + by);
                *(float2*)&C[(size_t)m0 * N + n0] = o0;
                *(float2*)&C[(size_t)(m0 + 8) * N + n0] = o1;
            }
        }
    }
}

// ---------------- im2col for patch embed (tf32-rounded output) ----------------
__global__ void im2col_kernel(const float* __restrict__ x, float* __restrict__ col) {
    int idx = blockIdx.x * blockDim.x + threadIdx.x;
    if (idx >= ROWS * K_PATCH) return;
    int k  = idx % K_PATCH;
    int bl = idx / K_PATCH;
    int l  = bl % L_SEQ;
    int b  = bl / L_SEQ;
    int c  = k / 256;
    int rem = k % 256;
    int i = rem / 16, j = rem % 16;
    int ph = l / 14, pw = l % 14;
    col[idx] = tf32r(x[((b*3 + c)*224 + ph*16 + i)*224 + pw*16 + j]);
}

// ---------------- fused residual add + LayerNorm (hn tf32-rounded) ----------------
__global__ void add_ln_kernel(const float* __restrict__ hidden, float* __restrict__ residual,
                              float* __restrict__ hn, const float* __restrict__ w,
                              const float* __restrict__ b, int first) {
    int row = blockIdx.x;
    int t = threadIdx.x;               // 192 threads
    int idx = row*D_MODEL + t;
    float h = hidden[idx];
    float r = first ? h : (residual[idx] + h);
    residual[idx] = r;
    __shared__ float red[6];
    float s = r;
    #pragma unroll
    for (int o = 16; o > 0; o >>= 1) s += __shfl_xor_sync(0xffffffffu, s, o);
    if ((t & 31) == 0) red[t >> 5] = s;
    __syncthreads();
    float mean = (red[0]+red[1]+red[2]+red[3]+red[4]+red[5]) * (1.f/192.f);
    __syncthreads();
    float dv = r - mean;
    s = dv*dv;
    #pragma unroll
    for (int o = 16; o > 0; o >>= 1) s += __shfl_xor_sync(0xffffffffu, s, o);
    if ((t & 31) == 0) red[t >> 5] = s;
    __syncthreads();
    float var = (red[0]+red[1]+red[2]+red[3]+red[4]+red[5]) * (1.f/192.f);
    hn[idx] = tf32r(dv * rsqrtf(var + 1e-5f) * w[t] + b[t]);
}

// ---------------- causal depthwise conv1d (k=4) + SiLU, sliding window ----------------
// grid (B_SZ, 4), block 384: thread d, chunk of 49 l's
__global__ __launch_bounds__(384) void conv_silu_kernel(
        const float* __restrict__ xz, const float* __restrict__ cw,
        const float* __restrict__ cb, float* __restrict__ xb) {
    int d = threadIdx.x;
    int b = blockIdx.x;
    int l0 = blockIdx.y * 49;
    float w0 = cw[d*D_CONV+0], w1 = cw[d*D_CONV+1], w2 = cw[d*D_CONV+2], w3 = cw[d*D_CONV+3];
    float bias = cb[d];
    size_t base = (size_t)b*L_SEQ*(2*D_INNER) + d;     // x-half
    size_t obase = (size_t)b*L_SEQ*D_INNER + d;
    float xm3 = (l0 >= 3) ? xz[base + (size_t)(l0-3)*(2*D_INNER)] : 0.f;
    float xm2 = (l0 >= 2) ? xz[base + (size_t)(l0-2)*(2*D_INNER)] : 0.f;
    float xm1 = (l0 >= 1) ? xz[base + (size_t)(l0-1)*(2*D_INNER)] : 0.f;
    #pragma unroll 7
    for (int l = l0; l < l0 + 49; l++) {
        float x0 = xz[base + (size_t)l*(2*D_INNER)];
        float acc = bias + w0*xm3 + w1*xm2 + w2*xm1 + w3*x0;
        float sig = 1.f / (1.f + __expf(-acc));
        xb[obase + (size_t)l*D_INNER] = acc * sig;
        xm3 = xm2; xm2 = xm1; xm1 = x0;
    }
}

// ---------------- selective scan: fused dt-proj + softplus + scan + z-gate ----------------
__global__ __launch_bounds__(128) void scan_kernel(
        const float* __restrict__ xb, const float* __restrict__ xdbl,
        const float* __restrict__ xz, const float* __restrict__ A_log,
        const float* __restrict__ Dskip, const float* __restrict__ dtw,
        const float* __restrict__ dtb, float* __restrict__ y) {
    int b = blockIdx.y;
    int d = blockIdx.x * 128 + threadIdx.x;
    __shared__ float sdbl[L_SEQ][XPROJ_N];          // 34496 B
    const float* src = &xdbl[(size_t)b*L_SEQ*XPROJ_N];
    for (int idx = threadIdx.x; idx < L_SEQ*XPROJ_N; idx += 128)
        ((float*)sdbl)[idx] = src[idx];
    __syncthreads();

    float wdt[DT_RANK];
    #pragma unroll
    for (int r = 0; r < DT_RANK; r++) wdt[r] = dtw[d*DT_RANK + r];
    float bdt = dtb[d];
    float a[D_STATE], h[D_STATE];
    #pragma unroll
    for (int n = 0; n < D_STATE; n++) {
        a[n] = -__expf(A_log[d*D_STATE + n]);
        h[n] = 0.f;
    }
    // detect geometric structure a[n] == a[0]*(n+1) -> exp via power chain
    bool structured = true;
    #pragma unroll
    for (int n = 0; n < D_STATE; n++)
        structured = structured && (a[n] == a[0]*(float)(n+1));
    float Dd = Dskip[d];

    size_t base0 = (size_t)b*L_SEQ*D_INNER + d;
    size_t zbase0 = (size_t)b*L_SEQ*(2*D_INNER) + D_INNER + d;
    float u_cur = xb[base0];
    float z_cur = xz[zbase0];
    for (int l = 0; l < L_SEQ; l++) {
        float u = u_cur, z = z_cur;
        if (l + 1 < L_SEQ) {
            u_cur = xb[base0 + (size_t)(l+1)*D_INNER];
            z_cur = xz[zbase0 + (size_t)(l+1)*(2*D_INNER)];
        }
        float dt = bdt;
        #pragma unroll
        for (int r = 0; r < DT_RANK; r++) dt += sdbl[l][r] * wdt[r];
        dt = (dt > 15.f) ? dt : __logf(1.f + __expf(dt));
        float du = dt * u;
        float e[D_STATE];
        if (structured) {
            float w = __expf(dt * a[0]);
            e[0] = w;
            float w2 = w * w;
            e[1] = w2;
            float w4 = w2 * w2;
            e[2] = w2 * w;  e[3] = w4;
            e[4] = w4 * w;  e[5] = w4 * w2;  e[6] = w4 * e[2]; e[7] = w4 * w4;
            #pragma unroll
            for (int n = 8; n < D_STATE; n++) e[n] = e[7] * e[n - 8];
        } else {
            #pragma unroll
            for (int n = 0; n < D_STATE; n++) e[n] = __expf(dt * a[n]);
        }
        float yv = 0.f;
        #pragma unroll
        for (int n = 0; n < D_STATE; n++) {
            h[n] = e[n] * h[n] + du * sdbl[l][DT_RANK + n];
            yv  += h[n] * sdbl[l][DT_RANK + D_STATE + n];
        }
        yv += u * Dd;
        float sig = 1.f / (1.f + __expf(-z));
        y[base0 + (size_t)l*D_INNER] = tf32r(yv * (z * sig));
    }
}

// ---------------- final: last-token residual+LN+head ----------------
__global__ void final_kernel(const float* __restrict__ residual, const float* __restrict__ hidden,
                             const float* __restrict__ nw, const float* __restrict__ nb,
                             const float* __restrict__ hw, const float* __restrict__ hb,
                             float* __restrict__ out) {
    int b = blockIdx.x;
    int t = threadIdx.x;               // 256 threads
    __shared__ float sh[D_MODEL];
    __shared__ float red[8];
    int row = b*L_SEQ + (L_SEQ - 1);
    float v = 0.f;
    if (t < D_MODEL) v = residual[row*D_MODEL + t] + hidden[row*D_MODEL + t];
    float s = v;
    #pragma unroll
    for (int o = 16; o > 0; o >>= 1) s += __shfl_xor_sync(0xffffffffu, s, o);
    if ((t & 31) == 0) red[t >> 5] = s;
    __syncthreads();
    float mean = 0.f;
    #pragma unroll
    for (int i = 0; i < 8; i++) mean += red[i];
    mean *= (1.f/192.f);
    __syncthreads();
    float dv = (t < D_MODEL) ? (v - mean) : 0.f;
    s = dv*dv;
    #pragma unroll
    for (int o = 16; o > 0; o >>= 1) s += __shfl_xor_sync(0xffffffffu, s, o);
    if ((t & 31) == 0) red[t >> 5] = s;
    __syncthreads();
    float var = 0.f;
    #pragma unroll
    for (int i = 0; i < 8; i++) var += red[i];
    var *= (1.f/192.f);
    if (t < D_MODEL) sh[t] = dv * rsqrtf(var + 1e-5f) * nw[t] + nb[t];
    __syncthreads();
    for (int o = t; o < N_CLS; o += 256) {
        float acc = hb[o];
        #pragma unroll 4
        for (int k = 0; k < D_MODEL; k++) acc += sh[k] * hw[o*D_MODEL + k];
        out[b*N_CLS + o] = acc;
    }
}

extern "C" void kernel_launch(void* const* d_in, const int* in_sizes, int n_in,
                              void* d_out, int out_size) {
    const float* x        = (const float*)d_in[0];
    const float* patch_w  = (const float*)d_in[1];
    const float* patch_b  = (const float*)d_in[2];
    const float* in_w     = (const float*)d_in[3];
    const float* conv_w   = (const float*)d_in[4];
    const float* conv_b   = (const float*)d_in[5];
    const float* xproj_w  = (const float*)d_in[6];
    const float* dt_w     = (const float*)d_in[7];
    const float* dt_b     = (const float*)d_in[8];
    const float* A_log    = (const float*)d_in[9];
    const float* D_skip   = (const float*)d_in[10];
    const float* out_w    = (const float*)d_in[11];
    const float* norm_w   = (const float*)d_in[12];
    const float* norm_b   = (const float*)d_in[13];
    const float* normf_w  = (const float*)d_in[14];
    const float* normf_b  = (const float*)d_in[15];
    const float* head_w   = (const float*)d_in[16];
    const float* head_b   = (const float*)d_in[17];
    float* out = (float*)d_out;

    float *hidden, *residual, *hn, *xz, *xb, *xdbl, *y;
    float *wpatch, *win, *wx, *wout;
    cudaGetSymbolAddress((void**)&hidden,   g_hidden);
    cudaGetSymbolAddress((void**)&residual, g_residual);
    cudaGetSymbolAddress((void**)&hn,       g_hn);
    cudaGetSymbolAddress((void**)&xz,       g_xz);
    cudaGetSymbolAddress((void**)&xb,       g_xb);
    cudaGetSymbolAddress((void**)&xdbl,     g_xdbl);
    cudaGetSymbolAddress((void**)&y,        g_y);
    cudaGetSymbolAddress((void**)&wpatch,   g_wpatch);
    cudaGetSymbolAddress((void**)&win,      g_win);
    cudaGetSymbolAddress((void**)&wx,       g_wx);
    cudaGetSymbolAddress((void**)&wout,     g_wout);

    const int smem_bytes = 2 * STAGE_BYTES;   // 55296
    cudaFuncSetAttribute(gemm_mma<true>,  cudaFuncAttributeMaxDynamicSharedMemorySize, smem_bytes);
    cudaFuncSetAttribute(gemm_mma<false>, cudaFuncAttributeMaxDynamicSharedMemorySize, smem_bytes);
    cudaFuncSetAttribute(gemm_mma<true>,  cudaFuncAttributePreferredSharedMemoryCarveout, 100);
    cudaFuncSetAttribute(gemm_mma<false>, cudaFuncAttributePreferredSharedMemoryCarveout, 100);

    // pre-round all GEMM weights to tf32 once
    round_tf32_kernel<<<512, 256>>>(patch_w, wpatch, D_MODEL*K_PATCH);
    round_tf32_kernel<<<2048, 256>>>(in_w,   win,    DEPTH*2*D_INNER*D_MODEL);
    round_tf32_kernel<<<512, 256>>>(xproj_w, wx,     DEPTH*XPROJ_N*D_INNER);
    round_tf32_kernel<<<1024, 256>>>(out_w,  wout,   DEPTH*D_MODEL*D_INNER);

    // patch embed: im2col (into xz scratch, tf32-rounded) + GEMM
    im2col_kernel<<<(ROWS*K_PATCH + 255)/256, 256>>>(x, xz);
    gemm_mma<true><<<dim3(3, ROWS/128), 256, smem_bytes>>>(xz, wpatch, hidden, ROWS, D_MODEL, K_PATCH, patch_b);

    for (int i = 0; i < DEPTH; i++) {
        add_ln_kernel<<<ROWS, D_MODEL>>>(hidden, residual, hn,
                                         norm_w + i*D_MODEL, norm_b + i*D_MODEL, i == 0);
        gemm_mma<true><<<dim3(12, ROWS/128), 256, smem_bytes>>>(hn, win + (size_t)i*2*D_INNER*D_MODEL,
                                                                xz, ROWS, 2*D_INNER, D_MODEL, nullptr);
        conv_silu_kernel<<<dim3(B_SZ, 4), 384>>>(xz, conv_w + i*D_INNER*D_CONV,
                                                 conv_b + i*D_INNER, xb);
        gemm_mma<false><<<dim3(1, ROWS/128), 256, smem_bytes>>>(xb, wx + (size_t)i*XPROJ_N*D_INNER,
                                                                xdbl, ROWS, XPROJ_N, D_INNER, nullptr);
        scan_kernel<<<dim3(D_INNER/128, B_SZ), 128>>>(xb, xdbl, xz,
                                                      A_log + (size_t)i*D_INNER*D_STATE,
                                                      D_skip + i*D_INNER,
                                                      dt_w + (size_t)i*D_INNER*DT_RANK,
                                                      dt_b + i*D_INNER, y);
        gemm_mma<true><<<dim3(3, ROWS/128), 256, smem_bytes>>>(y, wout + (size_t)i*D_MODEL*D_INNER,
                                                               hidden, ROWS, D_MODEL, D_INNER, nullptr);
    }

    final_kernel<<<B_SZ, 256>>>(residual, hidden, normf_w, normf_b, head_w, head_b, out);
}